// round 1
// baseline (speedup 1.0000x reference)
#include <cuda_runtime.h>
#include <math.h>

#define N_IMG   65536
#define IMG_D   2048
#define N_CLS   2048
#define ATT_D   1024
#define HC      512
#define TSOFT   10.0f
#define THRESH  0.17364817766693041f

// ---------------- scratch (static device memory; no allocation) ----------------
__device__ float g_a1[N_CLS * HC];          // a1 / a2 projection (reused)
__device__ float g_d[N_CLS * N_CLS];        // cosine-sim matrix (reused)
__device__ float g_attouts[N_CLS * ATT_D];  // encoded attributes
__device__ float g_protos[N_CLS * IMG_D];   // class prototypes (raw order)
__device__ int   g_count[N_CLS];
__device__ int   g_offset[N_CLS];
__device__ int   g_cursor[N_CLS];
__device__ int   g_perm[N_IMG];

// ---------------- segment mean: histogram / scan / scatter / gather ----------------
__global__ void zero_counts_kernel() {
    int i = blockIdx.x * blockDim.x + threadIdx.x;
    if (i < N_CLS) g_count[i] = 0;
}

__global__ void count_kernel(const int* __restrict__ labels) {
    int i = blockIdx.x * blockDim.x + threadIdx.x;
    if (i < N_IMG) atomicAdd(&g_count[labels[i]], 1);
}

// 1 block, 1024 threads: exclusive scan of 2048 counts -> g_offset, copy -> g_cursor
__global__ void scan_kernel() {
    __shared__ int a[N_CLS];
    __shared__ int b[1024];
    int t = threadIdx.x;
    a[2 * t]     = g_count[2 * t];
    a[2 * t + 1] = g_count[2 * t + 1];
    __syncthreads();
    b[t] = a[2 * t] + a[2 * t + 1];
    __syncthreads();
    for (int off = 1; off < 1024; off <<= 1) {
        int v = (t >= off) ? b[t - off] : 0;
        __syncthreads();
        b[t] += v;
        __syncthreads();
    }
    int excl = (t == 0) ? 0 : b[t - 1];
    g_offset[2 * t]     = excl;
    g_offset[2 * t + 1] = excl + a[2 * t];
    g_cursor[2 * t]     = excl;
    g_cursor[2 * t + 1] = excl + a[2 * t];
}

__global__ void scatter_kernel(const int* __restrict__ labels) {
    int i = blockIdx.x * blockDim.x + threadIdx.x;
    if (i < N_IMG) {
        int l = labels[i];
        int pos = atomicAdd(&g_cursor[l], 1);
        g_perm[pos] = i;
    }
}

// one block per class: mean of its image rows (coalesced float4)
__global__ void proto_kernel(const float* __restrict__ imgs) {
    int c = blockIdx.x;
    int t = threadIdx.x;  // 256 threads, 2048 cols -> 2 float4 per thread
    int cnt  = g_count[c];
    int base = g_offset[c];
    float4 acc0 = make_float4(0.f, 0.f, 0.f, 0.f);
    float4 acc1 = make_float4(0.f, 0.f, 0.f, 0.f);
    for (int r = 0; r < cnt; r++) {
        int row = g_perm[base + r];
        const float4* p = (const float4*)(imgs + (size_t)row * IMG_D);
        float4 v0 = p[t];
        float4 v1 = p[t + 256];
        acc0.x += v0.x; acc0.y += v0.y; acc0.z += v0.z; acc0.w += v0.w;
        acc1.x += v1.x; acc1.y += v1.y; acc1.z += v1.z; acc1.w += v1.w;
    }
    float inv = (cnt > 0) ? (1.0f / (float)cnt) : 0.0f;
    acc0.x *= inv; acc0.y *= inv; acc0.z *= inv; acc0.w *= inv;
    acc1.x *= inv; acc1.y *= inv; acc1.z *= inv; acc1.w *= inv;
    float4* o = (float4*)(g_protos + (size_t)c * IMG_D);
    o[t]       = acc0;
    o[t + 256] = acc1;
}

// ---------------- SGEMM: C[M,N] = A[M,K] @ (TB ? B[N,K]^T : B[K,N]) ----------------
// 128x64 block tile, 16 K-tile, 256 threads, 8x4 micro-tile. All dims multiples of tile.
template <bool TB>
__global__ __launch_bounds__(256)
void gemm_kernel(const float* __restrict__ A, const float* __restrict__ B,
                 float* __restrict__ C, int M, int N, int K) {
    const int BM = 128, BN = 64, BK = 16, TM = 8, TN = 4;
    __shared__ float As[BK][BM];
    __shared__ float Bs[BK][BN];
    int t  = threadIdx.x;
    int bm = blockIdx.y * BM;
    int bn = blockIdx.x * BN;
    int tx = t % 16;        // column group
    int ty = t / 16;        // row group
    float acc[TM][TN];
#pragma unroll
    for (int i = 0; i < TM; i++)
#pragma unroll
        for (int j = 0; j < TN; j++) acc[i][j] = 0.f;

    int ar = t / 4;             // 0..63 (rows ar, ar+64)
    int ak = (t % 4) * 4;       // k-offset in tile

    for (int kt = 0; kt < K; kt += BK) {
        // load A tile (transposed into smem)
#pragma unroll
        for (int h = 0; h < 2; h++) {
            float4 v = *(const float4*)(A + (size_t)(bm + ar + h * 64) * K + kt + ak);
            As[ak + 0][ar + h * 64] = v.x;
            As[ak + 1][ar + h * 64] = v.y;
            As[ak + 2][ar + h * 64] = v.z;
            As[ak + 3][ar + h * 64] = v.w;
        }
        if (TB) {
            // B[N,K] row-major: same layout as A, one float4 per thread (64 rows)
            int br = t / 4;
            int bk = (t % 4) * 4;
            float4 v = *(const float4*)(B + (size_t)(bn + br) * K + kt + bk);
            Bs[bk + 0][br] = v.x;
            Bs[bk + 1][br] = v.y;
            Bs[bk + 2][br] = v.z;
            Bs[bk + 3][br] = v.w;
        } else {
            // B[K,N] row-major: contiguous float4 store
            int bkr = t / 16;
            int bnq = (t % 16) * 4;
            float4 v = *(const float4*)(B + (size_t)(kt + bkr) * N + bn + bnq);
            *(float4*)&Bs[bkr][bnq] = v;
        }
        __syncthreads();
#pragma unroll
        for (int k = 0; k < BK; k++) {
            float a[TM], b[TN];
            float4 a0 = *(const float4*)&As[k][ty * TM];
            float4 a1 = *(const float4*)&As[k][ty * TM + 4];
            a[0] = a0.x; a[1] = a0.y; a[2] = a0.z; a[3] = a0.w;
            a[4] = a1.x; a[5] = a1.y; a[6] = a1.z; a[7] = a1.w;
            float4 b0 = *(const float4*)&Bs[k][tx * TN];
            b[0] = b0.x; b[1] = b0.y; b[2] = b0.z; b[3] = b0.w;
#pragma unroll
            for (int i = 0; i < TM; i++)
#pragma unroll
                for (int j = 0; j < TN; j++) acc[i][j] += a[i] * b[j];
        }
        __syncthreads();
    }
#pragma unroll
    for (int i = 0; i < TM; i++) {
        float4 v = make_float4(acc[i][0], acc[i][1], acc[i][2], acc[i][3]);
        *(float4*)(C + (size_t)(bm + ty * TM + i) * N + bn + tx * TN) = v;
    }
}

// ---------------- row L2-normalize (in place) ----------------
__global__ void normalize_kernel(float* __restrict__ X, int D) {
    int r = blockIdx.x;
    int t = threadIdx.x;  // 128
    float s = 0.f;
    for (int j = t; j < D; j += 128) {
        float v = X[(size_t)r * D + j];
        s += v * v;
    }
    __shared__ float red[128];
    red[t] = s;
    __syncthreads();
    for (int w = 64; w > 0; w >>= 1) {
        if (t < w) red[t] += red[t + w];
        __syncthreads();
    }
    float norm = fmaxf(sqrtf(red[0]), 1e-8f);
    float inv = 1.0f / norm;
    for (int j = t; j < D; j += 128) X[(size_t)r * D + j] *= inv;
}

// ---------------- fused masked softmax + sparse matmul ----------------
// out[i,:] = sum_j softmax_row(where(D>THRESH, D, NEG)*T)[j] * V[map?map[j]:j, :]
// Masked entries are EXACTLY zero after softmax (expf underflow), so iterating only
// selected entries is exact. One block per row.
__global__ __launch_bounds__(256)
void softmax_spmm_kernel(const float* __restrict__ Dm, const float* __restrict__ V,
                         const int* __restrict__ map, float* __restrict__ out, int vd) {
    __shared__ float sd[N_CLS];
    __shared__ float sred[256];
    __shared__ int   scnt[256];
    int i = blockIdx.x;
    int t = threadIdx.x;

    for (int j = t; j < N_CLS; j += 256) sd[j] = Dm[(size_t)i * N_CLS + j];
    __syncthreads();

    float lmax = -1e30f;
    int lcnt = 0;
    for (int j = t; j < N_CLS; j += 256) {
        float v = sd[j];
        if (v > THRESH) { lmax = fmaxf(lmax, v); lcnt++; }
    }
    sred[t] = lmax; scnt[t] = lcnt;
    __syncthreads();
    for (int w = 128; w > 0; w >>= 1) {
        if (t < w) { sred[t] = fmaxf(sred[t], sred[t + w]); scnt[t] += scnt[t + w]; }
        __syncthreads();
    }
    float m = sred[0];
    int cnt = scnt[0];
    __syncthreads();

    float lsum = 0.f;
    if (cnt > 0) {
        for (int j = t; j < N_CLS; j += 256) {
            float v = sd[j];
            if (v > THRESH) lsum += expf((v - m) * TSOFT);
        }
    }
    sred[t] = lsum;
    __syncthreads();
    for (int w = 128; w > 0; w >>= 1) {
        if (t < w) sred[t] += sred[t + w];
        __syncthreads();
    }
    float invS = (cnt > 0) ? (1.0f / sred[0]) : 0.f;
    __syncthreads();

    float acc[8];
#pragma unroll
    for (int q = 0; q < 8; q++) acc[q] = 0.f;
    int nq = vd >> 8;  // 4 (vd=1024) or 8 (vd=2048)

    for (int j = 0; j < N_CLS; j++) {
        float v = sd[j];
        bool sel = (cnt > 0) ? (v > THRESH) : true;
        if (sel) {
            float w = (cnt > 0) ? (expf((v - m) * TSOFT) * invS) : (1.0f / (float)N_CLS);
            int src = map ? map[j] : j;
            const float* vr = V + (size_t)src * vd;
            for (int q = 0; q < nq; q++) acc[q] += w * vr[t + q * 256];
        }
    }
    for (int q = 0; q < nq; q++) out[(size_t)i * vd + t + q * 256] = acc[q];
}

// ---------------- launch ----------------
extern "C" void kernel_launch(void* const* d_in, const int* in_sizes, int n_in,
                              void* d_out, int out_size) {
    const float* image      = (const float*)d_in[0];
    const float* attributes = (const float*)d_in[1];
    const int*   labels     = (const int*)d_in[2];
    const int*   tpl        = (const int*)d_in[3];
    const float* ga         = (const float*)d_in[4];
    const float* gv         = (const float*)d_in[5];
    float* out = (float*)d_out;

    float *a1p, *dp, *aop, *prp;
    cudaGetSymbolAddress((void**)&a1p, g_a1);
    cudaGetSymbolAddress((void**)&dp, g_d);
    cudaGetSymbolAddress((void**)&aop, g_attouts);
    cudaGetSymbolAddress((void**)&prp, g_protos);

    // prototypes (segment mean)
    zero_counts_kernel<<<(N_CLS + 255) / 256, 256>>>();
    count_kernel<<<N_IMG / 256, 256>>>(labels);
    scan_kernel<<<1, 1024>>>();
    scatter_kernel<<<N_IMG / 256, 256>>>(labels);
    proto_kernel<<<N_CLS, 256>>>(image);

    // a1 = attributes @ att_g_a ; normalize ; d1 = a1n @ a1n^T
    gemm_kernel<false><<<dim3(HC / 64, N_CLS / 128), 256>>>(attributes, ga, a1p, N_CLS, HC, ATT_D);
    normalize_kernel<<<N_CLS, 128>>>(a1p, HC);
    gemm_kernel<true><<<dim3(N_CLS / 64, N_CLS / 128), 256>>>(a1p, a1p, dp, N_CLS, N_CLS, HC);

    // att_outs = softmax(mask(d1)) @ attributes   (exact sparse)
    softmax_spmm_kernel<<<N_CLS, 256>>>(dp, attributes, nullptr, aop, ATT_D);

    // a2 = att_outs @ att_g_v ; normalize ; d2
    gemm_kernel<false><<<dim3(HC / 64, N_CLS / 128), 256>>>(aop, gv, a1p, N_CLS, HC, ATT_D);
    normalize_kernel<<<N_CLS, 128>>>(a1p, HC);
    gemm_kernel<true><<<dim3(N_CLS / 64, N_CLS / 128), 256>>>(a1p, a1p, dp, N_CLS, N_CLS, HC);

    // out = softmax(mask(d2)) @ protos[tpl]   (exact sparse)
    softmax_spmm_kernel<<<N_CLS, 256>>>(dp, prp, tpl, out, IMG_D);
}

// round 2
// speedup vs baseline: 1.2191x; 1.2191x over previous
#include <cuda_runtime.h>
#include <math.h>

#define N_IMG   65536
#define IMG_D   2048
#define N_CLS   2048
#define ATT_D   1024
#define HC      512
#define TSOFT   10.0f
#define THRESH  0.17364817766693041f

// ---------------- scratch (static device memory; no allocation) ----------------
__device__ float g_a1[N_CLS * HC];
__device__ float g_d[N_CLS * N_CLS];
__device__ float g_attouts[N_CLS * ATT_D];
__device__ float g_protos[N_CLS * IMG_D];
__device__ int   g_count[N_CLS];
__device__ int   g_offset[N_CLS];
__device__ int   g_cursor[N_CLS];
__device__ int   g_perm[N_IMG];

// ---------------- segment mean: histogram / scan / scatter / gather ----------------
__global__ void zero_counts_kernel() {
    int i = blockIdx.x * blockDim.x + threadIdx.x;
    if (i < N_CLS) g_count[i] = 0;
}

__global__ void count_kernel(const int* __restrict__ labels) {
    int i = blockIdx.x * blockDim.x + threadIdx.x;
    if (i < N_IMG) atomicAdd(&g_count[labels[i]], 1);
}

__global__ void scan_kernel() {
    __shared__ int a[N_CLS];
    __shared__ int b[1024];
    int t = threadIdx.x;
    a[2 * t]     = g_count[2 * t];
    a[2 * t + 1] = g_count[2 * t + 1];
    __syncthreads();
    b[t] = a[2 * t] + a[2 * t + 1];
    __syncthreads();
    for (int off = 1; off < 1024; off <<= 1) {
        int v = (t >= off) ? b[t - off] : 0;
        __syncthreads();
        b[t] += v;
        __syncthreads();
    }
    int excl = (t == 0) ? 0 : b[t - 1];
    g_offset[2 * t]     = excl;
    g_offset[2 * t + 1] = excl + a[2 * t];
    g_cursor[2 * t]     = excl;
    g_cursor[2 * t + 1] = excl + a[2 * t];
}

__global__ void scatter_kernel(const int* __restrict__ labels) {
    int i = blockIdx.x * blockDim.x + threadIdx.x;
    if (i < N_IMG) {
        int l = labels[i];
        int pos = atomicAdd(&g_cursor[l], 1);
        g_perm[pos] = i;
    }
}

// grid (N_CLS, 2), 256 threads: each block averages 1024 cols of one class
__global__ void proto_kernel(const float* __restrict__ imgs) {
    int c = blockIdx.x;
    int col = blockIdx.y * 1024 + threadIdx.x * 4;
    int cnt  = g_count[c];
    int base = g_offset[c];
    float4 acc = make_float4(0.f, 0.f, 0.f, 0.f);
    int r = 0;
    for (; r + 2 <= cnt; r += 2) {
        int i0 = g_perm[base + r];
        int i1 = g_perm[base + r + 1];
        float4 v0 = *(const float4*)(imgs + (size_t)i0 * IMG_D + col);
        float4 v1 = *(const float4*)(imgs + (size_t)i1 * IMG_D + col);
        acc.x += v0.x + v1.x; acc.y += v0.y + v1.y;
        acc.z += v0.z + v1.z; acc.w += v0.w + v1.w;
    }
    if (r < cnt) {
        int i0 = g_perm[base + r];
        float4 v0 = *(const float4*)(imgs + (size_t)i0 * IMG_D + col);
        acc.x += v0.x; acc.y += v0.y; acc.z += v0.z; acc.w += v0.w;
    }
    float inv = (cnt > 0) ? (1.0f / (float)cnt) : 0.0f;
    acc.x *= inv; acc.y *= inv; acc.z *= inv; acc.w *= inv;
    *(float4*)(g_protos + (size_t)c * IMG_D + col) = acc;
}

// ---------------- TF32 tensor-core GEMM ----------------
__device__ __forceinline__ float f2tf(float x) {
    unsigned r;
    asm("cvt.rna.tf32.f32 %0, %1;" : "=r"(r) : "f"(x));
    return __uint_as_float(r);
}

__device__ __forceinline__ void mma_tf32(float* c, const unsigned* a, const unsigned* b) {
    asm volatile(
        "mma.sync.aligned.m16n8k8.row.col.f32.tf32.tf32.f32 "
        "{%0,%1,%2,%3}, {%4,%5,%6,%7}, {%8,%9}, {%0,%1,%2,%3};"
        : "+f"(c[0]), "+f"(c[1]), "+f"(c[2]), "+f"(c[3])
        : "r"(a[0]), "r"(a[1]), "r"(a[2]), "r"(a[3]), "r"(b[0]), "r"(b[1]));
}

// C[M,N] = A[M,K] @ (TB ? B[N,K]^T : B[K,N]).  128x128x16 tiles, 8 warps.
// Dims must be multiples of 128 (M,N) and 16 (K). All true here.
template <bool TB>
__global__ __launch_bounds__(256)
void gemm_tc(const float* __restrict__ A, const float* __restrict__ B,
             float* __restrict__ C, int M, int N, int K) {
    const int BM = 128, BN = 128, BK = 16;
    const int SA = 20;                 // As: [m][k], row stride 20 (conflict-free frag reads)
    const int SBT = 20;                // Bs (TB): [n][k]
    const int SBN = 132;               // Bs (!TB): [k][n]
    const int BSZ = TB ? BN * SBT : BK * SBN;
    __shared__ float As[2][BM * SA];
    __shared__ float Bs[2][BSZ];

    int t = threadIdx.x;
    int warp = t >> 5, lane = t & 31, g = lane >> 2, tig = lane & 3;
    int bm = blockIdx.y * BM, bn = blockIdx.x * BN;
    int wm = (warp >> 1) * 32, wn = (warp & 1) * 64;

    int ar = t >> 2;                   // 0..63
    int ak = (t & 3) << 2;             // 0,4,8,12

    const float* Ag = A + (size_t)(bm + ar) * K + ak;
    const float* Bg = TB ? (B + (size_t)(bn + ar) * K + ak)
                         : (B + (size_t)(t >> 4) * N + bn + ((t & 15) << 2));

    float c[2][8][4];
#pragma unroll
    for (int mi = 0; mi < 2; mi++)
#pragma unroll
        for (int ni = 0; ni < 8; ni++)
#pragma unroll
            for (int q = 0; q < 4; q++) c[mi][ni][q] = 0.f;

    // prefetch tile 0
    float4 pA0 = *(const float4*)(Ag);
    float4 pA1 = *(const float4*)(Ag + (size_t)64 * K);
    float4 pB0, pB1;
    if (TB) { pB0 = *(const float4*)(Bg); pB1 = *(const float4*)(Bg + (size_t)64 * K); }
    else    { pB0 = *(const float4*)(Bg); pB1 = *(const float4*)(Bg + 64); }

    int buf = 0;
    // store tile 0
    {
        float* s = As[0] + ar * SA + ak;
        s[0] = f2tf(pA0.x); s[1] = f2tf(pA0.y); s[2] = f2tf(pA0.z); s[3] = f2tf(pA0.w);
        s += 64 * SA;
        s[0] = f2tf(pA1.x); s[1] = f2tf(pA1.y); s[2] = f2tf(pA1.z); s[3] = f2tf(pA1.w);
        if (TB) {
            float* sb = Bs[0] + ar * SBT + ak;
            sb[0] = f2tf(pB0.x); sb[1] = f2tf(pB0.y); sb[2] = f2tf(pB0.z); sb[3] = f2tf(pB0.w);
            sb += 64 * SBT;
            sb[0] = f2tf(pB1.x); sb[1] = f2tf(pB1.y); sb[2] = f2tf(pB1.z); sb[3] = f2tf(pB1.w);
        } else {
            float* sb = Bs[0] + (t >> 4) * SBN + ((t & 15) << 2);
            float4 w0 = make_float4(f2tf(pB0.x), f2tf(pB0.y), f2tf(pB0.z), f2tf(pB0.w));
            float4 w1 = make_float4(f2tf(pB1.x), f2tf(pB1.y), f2tf(pB1.z), f2tf(pB1.w));
            *(float4*)(sb) = w0;
            *(float4*)(sb + 64) = w1;
        }
    }
    __syncthreads();

    int T = K / BK;
    for (int kt = 0; kt < T; kt++) {
        bool has_next = (kt + 1 < T);
        if (has_next) {
            Ag += BK;
            pA0 = *(const float4*)(Ag);
            pA1 = *(const float4*)(Ag + (size_t)64 * K);
            if (TB) {
                Bg += BK;
                pB0 = *(const float4*)(Bg);
                pB1 = *(const float4*)(Bg + (size_t)64 * K);
            } else {
                Bg += (size_t)BK * N;
                pB0 = *(const float4*)(Bg);
                pB1 = *(const float4*)(Bg + 64);
            }
        }
        // compute current buffer
#pragma unroll
        for (int ks = 0; ks < BK; ks += 8) {
            unsigned a[2][4], bf[8][2];
#pragma unroll
            for (int mi = 0; mi < 2; mi++) {
                int rb = wm + mi * 16;
                a[mi][0] = __float_as_uint(As[buf][(rb + g) * SA + ks + tig]);
                a[mi][1] = __float_as_uint(As[buf][(rb + g + 8) * SA + ks + tig]);
                a[mi][2] = __float_as_uint(As[buf][(rb + g) * SA + ks + tig + 4]);
                a[mi][3] = __float_as_uint(As[buf][(rb + g + 8) * SA + ks + tig + 4]);
            }
#pragma unroll
            for (int ni = 0; ni < 8; ni++) {
                int cb = wn + ni * 8 + g;
                if (TB) {
                    bf[ni][0] = __float_as_uint(Bs[buf][cb * SBT + ks + tig]);
                    bf[ni][1] = __float_as_uint(Bs[buf][cb * SBT + ks + tig + 4]);
                } else {
                    bf[ni][0] = __float_as_uint(Bs[buf][(ks + tig) * SBN + cb]);
                    bf[ni][1] = __float_as_uint(Bs[buf][(ks + tig + 4) * SBN + cb]);
                }
            }
#pragma unroll
            for (int mi = 0; mi < 2; mi++)
#pragma unroll
                for (int ni = 0; ni < 8; ni++)
                    mma_tf32(c[mi][ni], a[mi], bf[ni]);
        }
        if (has_next) {
            int nb = buf ^ 1;
            float* s = As[nb] + ar * SA + ak;
            s[0] = f2tf(pA0.x); s[1] = f2tf(pA0.y); s[2] = f2tf(pA0.z); s[3] = f2tf(pA0.w);
            s += 64 * SA;
            s[0] = f2tf(pA1.x); s[1] = f2tf(pA1.y); s[2] = f2tf(pA1.z); s[3] = f2tf(pA1.w);
            if (TB) {
                float* sb = Bs[nb] + ar * SBT + ak;
                sb[0] = f2tf(pB0.x); sb[1] = f2tf(pB0.y); sb[2] = f2tf(pB0.z); sb[3] = f2tf(pB0.w);
                sb += 64 * SBT;
                sb[0] = f2tf(pB1.x); sb[1] = f2tf(pB1.y); sb[2] = f2tf(pB1.z); sb[3] = f2tf(pB1.w);
            } else {
                float* sb = Bs[nb] + (t >> 4) * SBN + ((t & 15) << 2);
                float4 w0 = make_float4(f2tf(pB0.x), f2tf(pB0.y), f2tf(pB0.z), f2tf(pB0.w));
                float4 w1 = make_float4(f2tf(pB1.x), f2tf(pB1.y), f2tf(pB1.z), f2tf(pB1.w));
                *(float4*)(sb) = w0;
                *(float4*)(sb + 64) = w1;
            }
            __syncthreads();
            buf = nb;
        }
    }

    // epilogue
#pragma unroll
    for (int mi = 0; mi < 2; mi++) {
#pragma unroll
        for (int ni = 0; ni < 8; ni++) {
            int row = bm + wm + mi * 16 + g;
            int col = bn + wn + ni * 8 + tig * 2;
            *(float2*)(C + (size_t)row * N + col) = make_float2(c[mi][ni][0], c[mi][ni][1]);
            *(float2*)(C + (size_t)(row + 8) * N + col) = make_float2(c[mi][ni][2], c[mi][ni][3]);
        }
    }
}

// ---------------- row L2-normalize (in place) ----------------
__global__ void normalize_kernel(float* __restrict__ X, int D) {
    int r = blockIdx.x;
    int t = threadIdx.x;  // 128
    float s = 0.f;
    for (int j = t; j < D; j += 128) {
        float v = X[(size_t)r * D + j];
        s += v * v;
    }
    __shared__ float red[128];
    red[t] = s;
    __syncthreads();
    for (int w = 64; w > 0; w >>= 1) {
        if (t < w) red[t] += red[t + w];
        __syncthreads();
    }
    float norm = fmaxf(sqrtf(red[0]), 1e-8f);
    float inv = 1.0f / norm;
    for (int j = t; j < D; j += 128) X[(size_t)r * D + j] *= inv;
}

// ---------------- fused masked softmax + sparse matmul (exact) ----------------
__global__ __launch_bounds__(256)
void softmax_spmm_kernel(const float* __restrict__ Dm, const float* __restrict__ V,
                         const int* __restrict__ map, float* __restrict__ out, int vd) {
    __shared__ float sd[N_CLS];
    __shared__ float sred[256];
    __shared__ int   scnt[256];
    int i = blockIdx.x;
    int t = threadIdx.x;

    for (int j = t; j < N_CLS; j += 256) sd[j] = Dm[(size_t)i * N_CLS + j];
    __syncthreads();

    float lmax = -1e30f;
    int lcnt = 0;
    for (int j = t; j < N_CLS; j += 256) {
        float v = sd[j];
        if (v > THRESH) { lmax = fmaxf(lmax, v); lcnt++; }
    }
    sred[t] = lmax; scnt[t] = lcnt;
    __syncthreads();
    for (int w = 128; w > 0; w >>= 1) {
        if (t < w) { sred[t] = fmaxf(sred[t], sred[t + w]); scnt[t] += scnt[t + w]; }
        __syncthreads();
    }
    float m = sred[0];
    int cnt = scnt[0];
    __syncthreads();

    float lsum = 0.f;
    if (cnt > 0) {
        for (int j = t; j < N_CLS; j += 256) {
            float v = sd[j];
            if (v > THRESH) lsum += expf((v - m) * TSOFT);
        }
    }
    sred[t] = lsum;
    __syncthreads();
    for (int w = 128; w > 0; w >>= 1) {
        if (t < w) sred[t] += sred[t + w];
        __syncthreads();
    }
    float invS = (cnt > 0) ? (1.0f / sred[0]) : 0.f;
    __syncthreads();

    float acc[8];
#pragma unroll
    for (int q = 0; q < 8; q++) acc[q] = 0.f;
    int nq = vd >> 8;

    for (int j = 0; j < N_CLS; j++) {
        float v = sd[j];
        bool sel = (cnt > 0) ? (v > THRESH) : true;
        if (sel) {
            float w = (cnt > 0) ? (expf((v - m) * TSOFT) * invS) : (1.0f / (float)N_CLS);
            int src = map ? map[j] : j;
            const float* vr = V + (size_t)src * vd;
            for (int q = 0; q < nq; q++) acc[q] += w * vr[t + q * 256];
        }
    }
    for (int q = 0; q < nq; q++) out[(size_t)i * vd + t + q * 256] = acc[q];
}

// ---------------- launch ----------------
extern "C" void kernel_launch(void* const* d_in, const int* in_sizes, int n_in,
                              void* d_out, int out_size) {
    const float* image      = (const float*)d_in[0];
    const float* attributes = (const float*)d_in[1];
    const int*   labels     = (const int*)d_in[2];
    const int*   tpl        = (const int*)d_in[3];
    const float* ga         = (const float*)d_in[4];
    const float* gv         = (const float*)d_in[5];
    float* out = (float*)d_out;

    float *a1p, *dp, *aop, *prp;
    cudaGetSymbolAddress((void**)&a1p, g_a1);
    cudaGetSymbolAddress((void**)&dp, g_d);
    cudaGetSymbolAddress((void**)&aop, g_attouts);
    cudaGetSymbolAddress((void**)&prp, g_protos);

    // prototypes (segment mean)
    zero_counts_kernel<<<(N_CLS + 255) / 256, 256>>>();
    count_kernel<<<N_IMG / 256, 256>>>(labels);
    scan_kernel<<<1, 1024>>>();
    scatter_kernel<<<N_IMG / 256, 256>>>(labels);
    proto_kernel<<<dim3(N_CLS, 2), 256>>>(image);

    // a1 = attributes @ att_g_a ; normalize ; d1 = a1n @ a1n^T
    gemm_tc<false><<<dim3(HC / 128, N_CLS / 128), 256>>>(attributes, ga, a1p, N_CLS, HC, ATT_D);
    normalize_kernel<<<N_CLS, 128>>>(a1p, HC);
    gemm_tc<true><<<dim3(N_CLS / 128, N_CLS / 128), 256>>>(a1p, a1p, dp, N_CLS, N_CLS, HC);

    // att_outs = softmax(mask(d1)) @ attributes   (exact sparse)
    softmax_spmm_kernel<<<N_CLS, 256>>>(dp, attributes, nullptr, aop, ATT_D);

    // a2 = att_outs @ att_g_v ; normalize ; d2
    gemm_tc<false><<<dim3(HC / 128, N_CLS / 128), 256>>>(aop, gv, a1p, N_CLS, HC, ATT_D);
    normalize_kernel<<<N_CLS, 128>>>(a1p, HC);
    gemm_tc<true><<<dim3(N_CLS / 128, N_CLS / 128), 256>>>(a1p, a1p, dp, N_CLS, N_CLS, HC);

    // out = softmax(mask(d2)) @ protos[tpl]   (exact sparse)
    softmax_spmm_kernel<<<N_CLS, 256>>>(dp, prp, tpl, out, IMG_D);
}

// round 3
// speedup vs baseline: 4.2949x; 3.5232x over previous
#include <cuda_runtime.h>
#include <math.h>

#define N_IMG   65536
#define IMG_D   2048
#define N_CLS   2048
#define ATT_D   1024
#define HC      512
#define TSOFT   10.0f
#define THRESH  0.17364817766693041f

// ---------------- scratch (static device memory; no allocation) ----------------
__device__ float g_a1[N_CLS * HC];
__device__ float g_d[N_CLS * N_CLS];
__device__ float g_attouts[N_CLS * ATT_D];
__device__ float g_protos[N_CLS * IMG_D];
__device__ int   g_count[N_CLS];
__device__ int   g_offset[N_CLS];
__device__ int   g_cursor[N_CLS];
__device__ int   g_perm[N_IMG];

// ---------------- segment mean: histogram / scan / scatter / gather ----------------
__global__ void zero_counts_kernel() {
    int i = blockIdx.x * blockDim.x + threadIdx.x;
    if (i < N_CLS) g_count[i] = 0;
}

__global__ void count_kernel(const int* __restrict__ labels) {
    int i = blockIdx.x * blockDim.x + threadIdx.x;
    if (i < N_IMG) atomicAdd(&g_count[labels[i]], 1);
}

__global__ void scan_kernel() {
    __shared__ int a[N_CLS];
    __shared__ int b[1024];
    int t = threadIdx.x;
    a[2 * t]     = g_count[2 * t];
    a[2 * t + 1] = g_count[2 * t + 1];
    __syncthreads();
    b[t] = a[2 * t] + a[2 * t + 1];
    __syncthreads();
    for (int off = 1; off < 1024; off <<= 1) {
        int v = (t >= off) ? b[t - off] : 0;
        __syncthreads();
        b[t] += v;
        __syncthreads();
    }
    int excl = (t == 0) ? 0 : b[t - 1];
    g_offset[2 * t]     = excl;
    g_offset[2 * t + 1] = excl + a[2 * t];
    g_cursor[2 * t]     = excl;
    g_cursor[2 * t + 1] = excl + a[2 * t];
}

__global__ void scatter_kernel(const int* __restrict__ labels) {
    int i = blockIdx.x * blockDim.x + threadIdx.x;
    if (i < N_IMG) {
        int l = labels[i];
        int pos = atomicAdd(&g_cursor[l], 1);
        g_perm[pos] = i;
    }
}

// grid (N_CLS, 2), 256 threads: each block averages 1024 cols of one class
__global__ void proto_kernel(const float* __restrict__ imgs) {
    int c = blockIdx.x;
    int col = blockIdx.y * 1024 + threadIdx.x * 4;
    int cnt  = g_count[c];
    int base = g_offset[c];
    float4 acc = make_float4(0.f, 0.f, 0.f, 0.f);
    int r = 0;
    for (; r + 4 <= cnt; r += 4) {
        int i0 = g_perm[base + r];
        int i1 = g_perm[base + r + 1];
        int i2 = g_perm[base + r + 2];
        int i3 = g_perm[base + r + 3];
        float4 v0 = *(const float4*)(imgs + (size_t)i0 * IMG_D + col);
        float4 v1 = *(const float4*)(imgs + (size_t)i1 * IMG_D + col);
        float4 v2 = *(const float4*)(imgs + (size_t)i2 * IMG_D + col);
        float4 v3 = *(const float4*)(imgs + (size_t)i3 * IMG_D + col);
        acc.x += (v0.x + v1.x) + (v2.x + v3.x);
        acc.y += (v0.y + v1.y) + (v2.y + v3.y);
        acc.z += (v0.z + v1.z) + (v2.z + v3.z);
        acc.w += (v0.w + v1.w) + (v2.w + v3.w);
    }
    for (; r < cnt; r++) {
        int i0 = g_perm[base + r];
        float4 v0 = *(const float4*)(imgs + (size_t)i0 * IMG_D + col);
        acc.x += v0.x; acc.y += v0.y; acc.z += v0.z; acc.w += v0.w;
    }
    float inv = (cnt > 0) ? (1.0f / (float)cnt) : 0.0f;
    acc.x *= inv; acc.y *= inv; acc.z *= inv; acc.w *= inv;
    *(float4*)(g_protos + (size_t)c * IMG_D + col) = acc;
}

// ---------------- TF32 tensor-core GEMM ----------------
__device__ __forceinline__ float f2tf(float x) {
    unsigned r;
    asm("cvt.rna.tf32.f32 %0, %1;" : "=r"(r) : "f"(x));
    return __uint_as_float(r);
}

__device__ __forceinline__ void mma_tf32(float* c, const unsigned* a, const unsigned* b) {
    asm volatile(
        "mma.sync.aligned.m16n8k8.row.col.f32.tf32.tf32.f32 "
        "{%0,%1,%2,%3}, {%4,%5,%6,%7}, {%8,%9}, {%0,%1,%2,%3};"
        : "+f"(c[0]), "+f"(c[1]), "+f"(c[2]), "+f"(c[3])
        : "r"(a[0]), "r"(a[1]), "r"(a[2]), "r"(a[3]), "r"(b[0]), "r"(b[1]));
}

// C[M,N] = A[M,K] @ (TB ? B[N,K]^T : B[K,N]).  128x128x16 tiles, 8 warps.
template <bool TB>
__global__ __launch_bounds__(256)
void gemm_tc(const float* __restrict__ A, const float* __restrict__ B,
             float* __restrict__ C, int M, int N, int K) {
    const int BM = 128, BN = 128, BK = 16;
    const int SA = 20;
    const int SBT = 20;
    const int SBN = 132;
    const int BSZ = TB ? BN * SBT : BK * SBN;
    __shared__ float As[2][BM * SA];
    __shared__ float Bs[2][BSZ];

    int t = threadIdx.x;
    int warp = t >> 5, lane = t & 31, g = lane >> 2, tig = lane & 3;
    int bm = blockIdx.y * BM, bn = blockIdx.x * BN;
    int wm = (warp >> 1) * 32, wn = (warp & 1) * 64;

    int ar = t >> 2;
    int ak = (t & 3) << 2;

    const float* Ag = A + (size_t)(bm + ar) * K + ak;
    const float* Bg = TB ? (B + (size_t)(bn + ar) * K + ak)
                         : (B + (size_t)(t >> 4) * N + bn + ((t & 15) << 2));

    float c[2][8][4];
#pragma unroll
    for (int mi = 0; mi < 2; mi++)
#pragma unroll
        for (int ni = 0; ni < 8; ni++)
#pragma unroll
            for (int q = 0; q < 4; q++) c[mi][ni][q] = 0.f;

    float4 pA0 = *(const float4*)(Ag);
    float4 pA1 = *(const float4*)(Ag + (size_t)64 * K);
    float4 pB0, pB1;
    if (TB) { pB0 = *(const float4*)(Bg); pB1 = *(const float4*)(Bg + (size_t)64 * K); }
    else    { pB0 = *(const float4*)(Bg); pB1 = *(const float4*)(Bg + 64); }

    int buf = 0;
    {
        float* s = As[0] + ar * SA + ak;
        s[0] = f2tf(pA0.x); s[1] = f2tf(pA0.y); s[2] = f2tf(pA0.z); s[3] = f2tf(pA0.w);
        s += 64 * SA;
        s[0] = f2tf(pA1.x); s[1] = f2tf(pA1.y); s[2] = f2tf(pA1.z); s[3] = f2tf(pA1.w);
        if (TB) {
            float* sb = Bs[0] + ar * SBT + ak;
            sb[0] = f2tf(pB0.x); sb[1] = f2tf(pB0.y); sb[2] = f2tf(pB0.z); sb[3] = f2tf(pB0.w);
            sb += 64 * SBT;
            sb[0] = f2tf(pB1.x); sb[1] = f2tf(pB1.y); sb[2] = f2tf(pB1.z); sb[3] = f2tf(pB1.w);
        } else {
            float* sb = Bs[0] + (t >> 4) * SBN + ((t & 15) << 2);
            float4 w0 = make_float4(f2tf(pB0.x), f2tf(pB0.y), f2tf(pB0.z), f2tf(pB0.w));
            float4 w1 = make_float4(f2tf(pB1.x), f2tf(pB1.y), f2tf(pB1.z), f2tf(pB1.w));
            *(float4*)(sb) = w0;
            *(float4*)(sb + 64) = w1;
        }
    }
    __syncthreads();

    int T = K / BK;
    for (int kt = 0; kt < T; kt++) {
        bool has_next = (kt + 1 < T);
        if (has_next) {
            Ag += BK;
            pA0 = *(const float4*)(Ag);
            pA1 = *(const float4*)(Ag + (size_t)64 * K);
            if (TB) {
                Bg += BK;
                pB0 = *(const float4*)(Bg);
                pB1 = *(const float4*)(Bg + (size_t)64 * K);
            } else {
                Bg += (size_t)BK * N;
                pB0 = *(const float4*)(Bg);
                pB1 = *(const float4*)(Bg + 64);
            }
        }
#pragma unroll
        for (int ks = 0; ks < BK; ks += 8) {
            unsigned a[2][4], bf[8][2];
#pragma unroll
            for (int mi = 0; mi < 2; mi++) {
                int rb = wm + mi * 16;
                a[mi][0] = __float_as_uint(As[buf][(rb + g) * SA + ks + tig]);
                a[mi][1] = __float_as_uint(As[buf][(rb + g + 8) * SA + ks + tig]);
                a[mi][2] = __float_as_uint(As[buf][(rb + g) * SA + ks + tig + 4]);
                a[mi][3] = __float_as_uint(As[buf][(rb + g + 8) * SA + ks + tig + 4]);
            }
#pragma unroll
            for (int ni = 0; ni < 8; ni++) {
                int cb = wn + ni * 8 + g;
                if (TB) {
                    bf[ni][0] = __float_as_uint(Bs[buf][cb * SBT + ks + tig]);
                    bf[ni][1] = __float_as_uint(Bs[buf][cb * SBT + ks + tig + 4]);
                } else {
                    bf[ni][0] = __float_as_uint(Bs[buf][(ks + tig) * SBN + cb]);
                    bf[ni][1] = __float_as_uint(Bs[buf][(ks + tig + 4) * SBN + cb]);
                }
            }
#pragma unroll
            for (int mi = 0; mi < 2; mi++)
#pragma unroll
                for (int ni = 0; ni < 8; ni++)
                    mma_tf32(c[mi][ni], a[mi], bf[ni]);
        }
        if (has_next) {
            int nb = buf ^ 1;
            float* s = As[nb] + ar * SA + ak;
            s[0] = f2tf(pA0.x); s[1] = f2tf(pA0.y); s[2] = f2tf(pA0.z); s[3] = f2tf(pA0.w);
            s += 64 * SA;
            s[0] = f2tf(pA1.x); s[1] = f2tf(pA1.y); s[2] = f2tf(pA1.z); s[3] = f2tf(pA1.w);
            if (TB) {
                float* sb = Bs[nb] + ar * SBT + ak;
                sb[0] = f2tf(pB0.x); sb[1] = f2tf(pB0.y); sb[2] = f2tf(pB0.z); sb[3] = f2tf(pB0.w);
                sb += 64 * SBT;
                sb[0] = f2tf(pB1.x); sb[1] = f2tf(pB1.y); sb[2] = f2tf(pB1.z); sb[3] = f2tf(pB1.w);
            } else {
                float* sb = Bs[nb] + (t >> 4) * SBN + ((t & 15) << 2);
                float4 w0 = make_float4(f2tf(pB0.x), f2tf(pB0.y), f2tf(pB0.z), f2tf(pB0.w));
                float4 w1 = make_float4(f2tf(pB1.x), f2tf(pB1.y), f2tf(pB1.z), f2tf(pB1.w));
                *(float4*)(sb) = w0;
                *(float4*)(sb + 64) = w1;
            }
            __syncthreads();
            buf = nb;
        }
    }

#pragma unroll
    for (int mi = 0; mi < 2; mi++) {
#pragma unroll
        for (int ni = 0; ni < 8; ni++) {
            int row = bm + wm + mi * 16 + g;
            int col = bn + wn + ni * 8 + tig * 2;
            *(float2*)(C + (size_t)row * N + col) = make_float2(c[mi][ni][0], c[mi][ni][1]);
            *(float2*)(C + (size_t)(row + 8) * N + col) = make_float2(c[mi][ni][2], c[mi][ni][3]);
        }
    }
}

// ---------------- row L2-normalize (in place) ----------------
__global__ void normalize_kernel(float* __restrict__ X, int D) {
    int r = blockIdx.x;
    int t = threadIdx.x;  // 128
    float s = 0.f;
    for (int j = t; j < D; j += 128) {
        float v = X[(size_t)r * D + j];
        s += v * v;
    }
    __shared__ float red[128];
    red[t] = s;
    __syncthreads();
    for (int w = 64; w > 0; w >>= 1) {
        if (t < w) red[t] += red[t + w];
        __syncthreads();
    }
    float norm = fmaxf(sqrtf(red[0]), 1e-8f);
    float inv = 1.0f / norm;
    for (int j = t; j < D; j += 128) X[(size_t)r * D + j] *= inv;
}

// ---------------- fused masked softmax + sparse matmul (exact, compacted) ----------------
// Each thread owns 8 row entries in registers. Block reduces max, scans selected
// counts (deterministic compaction order), builds compact (idx, weight) list, and
// accumulates only the selected rows of V. Masked entries are exactly zero after
// softmax, so this is exact.
__global__ __launch_bounds__(256)
void softmax_spmm_kernel(const float* __restrict__ Dm, const float* __restrict__ V,
                         const int* __restrict__ map, float* __restrict__ out, int vd) {
    __shared__ float sred[256];
    __shared__ int   sscan[256];
    __shared__ int   sel_idx[N_CLS];
    __shared__ float sel_w[N_CLS];

    int i = blockIdx.x;
    int t = threadIdx.x;
    const float* row = Dm + (size_t)i * N_CLS;

    float v[8];
#pragma unroll
    for (int q = 0; q < 8; q++) v[q] = row[t + q * 256];

    // local max + count over selected entries
    float lmax = -1e30f;
    int lcnt = 0;
#pragma unroll
    for (int q = 0; q < 8; q++) {
        if (v[q] > THRESH) { lmax = fmaxf(lmax, v[q]); lcnt++; }
    }

    // block max reduce + inclusive scan of counts (Hillis-Steele)
    sred[t] = lmax;
    sscan[t] = lcnt;
    __syncthreads();
    for (int w = 128; w > 0; w >>= 1) {
        if (t < w) sred[t] = fmaxf(sred[t], sred[t + w]);
        __syncthreads();
    }
    float m = sred[0];
    __syncthreads();
    for (int off = 1; off < 256; off <<= 1) {
        int val = (t >= off) ? sscan[t - off] : 0;
        __syncthreads();
        sscan[t] += val;
        __syncthreads();
    }
    int cnt = sscan[255];
    int base = sscan[t] - lcnt;  // exclusive prefix for this thread

    float acc[8];
#pragma unroll
    for (int q = 0; q < 8; q++) acc[q] = 0.f;
    int nq = vd >> 8;

    if (cnt > 0) {
        // sum of exp over selected
        float lsum = 0.f;
#pragma unroll
        for (int q = 0; q < 8; q++) {
            if (v[q] > THRESH) lsum += expf((v[q] - m) * TSOFT);
        }
        __syncthreads();
        sred[t] = lsum;
        __syncthreads();
        for (int w = 128; w > 0; w >>= 1) {
            if (t < w) sred[t] += sred[t + w];
            __syncthreads();
        }
        float invS = 1.0f / sred[0];

        // deterministic compaction
        int pos = base;
#pragma unroll
        for (int q = 0; q < 8; q++) {
            if (v[q] > THRESH) {
                sel_idx[pos] = t + q * 256;
                sel_w[pos] = expf((v[q] - m) * TSOFT) * invS;
                pos++;
            }
        }
        __syncthreads();

        for (int s = 0; s < cnt; s++) {
            int j = sel_idx[s];
            float w = sel_w[s];
            int src = map ? map[j] : j;
            const float* vr = V + (size_t)src * vd;
#pragma unroll
            for (int q = 0; q < 8; q++)
                if (q < nq) acc[q] += w * vr[t + q * 256];
        }
    } else {
        // uniform fallback (never taken with this data; kept for exactness)
        float w = 1.0f / (float)N_CLS;
        for (int j = 0; j < N_CLS; j++) {
            int src = map ? map[j] : j;
            const float* vr = V + (size_t)src * vd;
#pragma unroll
            for (int q = 0; q < 8; q++)
                if (q < nq) acc[q] += w * vr[t + q * 256];
        }
    }

#pragma unroll
    for (int q = 0; q < 8; q++)
        if (q < nq) out[(size_t)i * vd + t + q * 256] = acc[q];
}

// ---------------- launch ----------------
extern "C" void kernel_launch(void* const* d_in, const int* in_sizes, int n_in,
                              void* d_out, int out_size) {
    const float* image      = (const float*)d_in[0];
    const float* attributes = (const float*)d_in[1];
    const int*   labels     = (const int*)d_in[2];
    const int*   tpl        = (const int*)d_in[3];
    const float* ga         = (const float*)d_in[4];
    const float* gv         = (const float*)d_in[5];
    float* out = (float*)d_out;

    float *a1p, *dp, *aop, *prp;
    cudaGetSymbolAddress((void**)&a1p, g_a1);
    cudaGetSymbolAddress((void**)&dp, g_d);
    cudaGetSymbolAddress((void**)&aop, g_attouts);
    cudaGetSymbolAddress((void**)&prp, g_protos);

    // prototypes (segment mean)
    zero_counts_kernel<<<(N_CLS + 255) / 256, 256>>>();
    count_kernel<<<N_IMG / 256, 256>>>(labels);
    scan_kernel<<<1, 1024>>>();
    scatter_kernel<<<N_IMG / 256, 256>>>(labels);
    proto_kernel<<<dim3(N_CLS, 2), 256>>>(image);

    // a1 = attributes @ att_g_a ; normalize ; d1 = a1n @ a1n^T
    gemm_tc<false><<<dim3(HC / 128, N_CLS / 128), 256>>>(attributes, ga, a1p, N_CLS, HC, ATT_D);
    normalize_kernel<<<N_CLS, 128>>>(a1p, HC);
    gemm_tc<true><<<dim3(N_CLS / 128, N_CLS / 128), 256>>>(a1p, a1p, dp, N_CLS, N_CLS, HC);

    // att_outs = softmax(mask(d1)) @ attributes   (exact sparse)
    softmax_spmm_kernel<<<N_CLS, 256>>>(dp, attributes, nullptr, aop, ATT_D);

    // a2 = att_outs @ att_g_v ; normalize ; d2
    gemm_tc<false><<<dim3(HC / 128, N_CLS / 128), 256>>>(aop, gv, a1p, N_CLS, HC, ATT_D);
    normalize_kernel<<<N_CLS, 128>>>(a1p, HC);
    gemm_tc<true><<<dim3(N_CLS / 128, N_CLS / 128), 256>>>(a1p, a1p, dp, N_CLS, N_CLS, HC);

    // out = softmax(mask(d2)) @ protos[tpl]   (exact sparse)
    softmax_spmm_kernel<<<N_CLS, 256>>>(dp, prp, tpl, out, IMG_D);
}

// round 4
// speedup vs baseline: 4.7436x; 1.1045x over previous
#include <cuda_runtime.h>
#include <math.h>

#define N_IMG   65536
#define IMG_D   2048
#define N_CLS   2048
#define ATT_D   1024
#define HC      512
#define TSOFT   10.0f
#define THRESH  0.17364817766693041f

// ---------------- scratch (static device memory; no allocation) ----------------
__device__ float g_a1[N_CLS * HC];
__device__ float g_d[N_CLS * N_CLS];
__device__ float g_attouts[N_CLS * ATT_D];
__device__ float g_protos[N_CLS * IMG_D];
__device__ int   g_count[N_CLS];
__device__ int   g_offset[N_CLS];
__device__ int   g_cursor[N_CLS];
__device__ int   g_perm[N_IMG];

// ---------------- segment mean: histogram / scan / scatter / gather ----------------
__global__ void zero_counts_kernel() {
    int i = blockIdx.x * blockDim.x + threadIdx.x;
    if (i < N_CLS) g_count[i] = 0;
}

__global__ void count_kernel(const int* __restrict__ labels) {
    int i = blockIdx.x * blockDim.x + threadIdx.x;
    if (i < N_IMG) atomicAdd(&g_count[labels[i]], 1);
}

__global__ void scan_kernel() {
    __shared__ int a[N_CLS];
    __shared__ int b[1024];
    int t = threadIdx.x;
    a[2 * t]     = g_count[2 * t];
    a[2 * t + 1] = g_count[2 * t + 1];
    __syncthreads();
    b[t] = a[2 * t] + a[2 * t + 1];
    __syncthreads();
    for (int off = 1; off < 1024; off <<= 1) {
        int v = (t >= off) ? b[t - off] : 0;
        __syncthreads();
        b[t] += v;
        __syncthreads();
    }
    int excl = (t == 0) ? 0 : b[t - 1];
    g_offset[2 * t]     = excl;
    g_offset[2 * t + 1] = excl + a[2 * t];
    g_cursor[2 * t]     = excl;
    g_cursor[2 * t + 1] = excl + a[2 * t];
}

__global__ void scatter_kernel(const int* __restrict__ labels) {
    int i = blockIdx.x * blockDim.x + threadIdx.x;
    if (i < N_IMG) {
        int l = labels[i];
        int pos = atomicAdd(&g_cursor[l], 1);
        g_perm[pos] = i;
    }
}

// grid (N_CLS, 2), 256 threads: each block averages 1024 cols of one class
__global__ void proto_kernel(const float* __restrict__ imgs) {
    int c = blockIdx.x;
    int col = blockIdx.y * 1024 + threadIdx.x * 4;
    int cnt  = g_count[c];
    int base = g_offset[c];
    float4 acc = make_float4(0.f, 0.f, 0.f, 0.f);
    int r = 0;
    for (; r + 4 <= cnt; r += 4) {
        int i0 = g_perm[base + r];
        int i1 = g_perm[base + r + 1];
        int i2 = g_perm[base + r + 2];
        int i3 = g_perm[base + r + 3];
        float4 v0 = *(const float4*)(imgs + (size_t)i0 * IMG_D + col);
        float4 v1 = *(const float4*)(imgs + (size_t)i1 * IMG_D + col);
        float4 v2 = *(const float4*)(imgs + (size_t)i2 * IMG_D + col);
        float4 v3 = *(const float4*)(imgs + (size_t)i3 * IMG_D + col);
        acc.x += (v0.x + v1.x) + (v2.x + v3.x);
        acc.y += (v0.y + v1.y) + (v2.y + v3.y);
        acc.z += (v0.z + v1.z) + (v2.z + v3.z);
        acc.w += (v0.w + v1.w) + (v2.w + v3.w);
    }
    for (; r < cnt; r++) {
        int i0 = g_perm[base + r];
        float4 v0 = *(const float4*)(imgs + (size_t)i0 * IMG_D + col);
        acc.x += v0.x; acc.y += v0.y; acc.z += v0.z; acc.w += v0.w;
    }
    float inv = (cnt > 0) ? (1.0f / (float)cnt) : 0.0f;
    acc.x *= inv; acc.y *= inv; acc.z *= inv; acc.w *= inv;
    *(float4*)(g_protos + (size_t)c * IMG_D + col) = acc;
}

// ---------------- TF32 tensor-core GEMM ----------------
__device__ __forceinline__ float f2tf(float x) {
    unsigned r;
    asm("cvt.rna.tf32.f32 %0, %1;" : "=r"(r) : "f"(x));
    return __uint_as_float(r);
}

__device__ __forceinline__ void mma_tf32(float* c, const unsigned* a, const unsigned* b) {
    asm volatile(
        "mma.sync.aligned.m16n8k8.row.col.f32.tf32.tf32.f32 "
        "{%0,%1,%2,%3}, {%4,%5,%6,%7}, {%8,%9}, {%0,%1,%2,%3};"
        : "+f"(c[0]), "+f"(c[1]), "+f"(c[2]), "+f"(c[3])
        : "r"(a[0]), "r"(a[1]), "r"(a[2]), "r"(a[3]), "r"(b[0]), "r"(b[1]));
}

// C[M,N] = A[M,K] @ (TB ? B[N,K]^T : B[K,N]).  128xBN x16 tiles, 8 warps.
// SYM: A==B (NT self-similarity); launch 1D triangular grid; compute upper
// blocks only and mirror-write the transpose (values bit-identical).
template <bool TB, int BN, bool SYM>
__global__ __launch_bounds__(256)
void gemm_tc(const float* __restrict__ A, const float* __restrict__ B,
             float* __restrict__ C, int M, int N, int K) {
    const int BM = 128, BK = 16;
    const int NFRAG = BN / 16;          // 8-wide n-fragments per warp
    const int SA = 20;
    const int SBT = 20;
    const int SBN = BN + 4;
    const int BSZ = TB ? BN * SBT : BK * SBN;
    __shared__ float As[2][BM * SA];
    __shared__ float Bs[2][BSZ];

    int t = threadIdx.x;
    int warp = t >> 5, lane = t & 31, g = lane >> 2, tig = lane & 3;

    int bm, bn;
    if (SYM) {
        int bi = blockIdx.x, r = 0, rowlen = N / 128;
        while (bi >= rowlen) { bi -= rowlen; r++; rowlen--; }
        bm = r * 128;
        bn = (r + bi) * 128;   // bn >= bm
    } else {
        bm = blockIdx.y * BM;
        bn = blockIdx.x * BN;
    }
    int wm = (warp >> 1) * 32, wn = (warp & 1) * (BN / 2);

    int ar = t >> 2;
    int ak = (t & 3) << 2;

    const float* Ag = A + (size_t)(bm + ar) * K + ak;
    const float* Bg = TB ? (B + (size_t)(bn + ar) * K + ak)
                         : (B + (size_t)(t >> 4) * N + bn + ((t & 15) << 2));

    float c[2][NFRAG][4];
#pragma unroll
    for (int mi = 0; mi < 2; mi++)
#pragma unroll
        for (int ni = 0; ni < NFRAG; ni++)
#pragma unroll
            for (int q = 0; q < 4; q++) c[mi][ni][q] = 0.f;

    float4 pA0 = *(const float4*)(Ag);
    float4 pA1 = *(const float4*)(Ag + (size_t)64 * K);
    float4 pB0, pB1;
    if (TB) { pB0 = *(const float4*)(Bg); pB1 = *(const float4*)(Bg + (size_t)64 * K); }
    else    { pB0 = *(const float4*)(Bg); if (BN == 128) pB1 = *(const float4*)(Bg + 64); }

    int buf = 0;
    {
        float* s = As[0] + ar * SA + ak;
        s[0] = f2tf(pA0.x); s[1] = f2tf(pA0.y); s[2] = f2tf(pA0.z); s[3] = f2tf(pA0.w);
        s += 64 * SA;
        s[0] = f2tf(pA1.x); s[1] = f2tf(pA1.y); s[2] = f2tf(pA1.z); s[3] = f2tf(pA1.w);
        if (TB) {
            float* sb = Bs[0] + ar * SBT + ak;
            sb[0] = f2tf(pB0.x); sb[1] = f2tf(pB0.y); sb[2] = f2tf(pB0.z); sb[3] = f2tf(pB0.w);
            sb += 64 * SBT;
            sb[0] = f2tf(pB1.x); sb[1] = f2tf(pB1.y); sb[2] = f2tf(pB1.z); sb[3] = f2tf(pB1.w);
        } else {
            float* sb = Bs[0] + (t >> 4) * SBN + ((t & 15) << 2);
            float4 w0 = make_float4(f2tf(pB0.x), f2tf(pB0.y), f2tf(pB0.z), f2tf(pB0.w));
            *(float4*)(sb) = w0;
            if (BN == 128) {
                float4 w1 = make_float4(f2tf(pB1.x), f2tf(pB1.y), f2tf(pB1.z), f2tf(pB1.w));
                *(float4*)(sb + 64) = w1;
            }
        }
    }
    __syncthreads();

    int T = K / BK;
    for (int kt = 0; kt < T; kt++) {
        bool has_next = (kt + 1 < T);
        if (has_next) {
            Ag += BK;
            pA0 = *(const float4*)(Ag);
            pA1 = *(const float4*)(Ag + (size_t)64 * K);
            if (TB) {
                Bg += BK;
                pB0 = *(const float4*)(Bg);
                pB1 = *(const float4*)(Bg + (size_t)64 * K);
            } else {
                Bg += (size_t)BK * N;
                pB0 = *(const float4*)(Bg);
                if (BN == 128) pB1 = *(const float4*)(Bg + 64);
            }
        }
#pragma unroll
        for (int ks = 0; ks < BK; ks += 8) {
            unsigned a[2][4], bf[NFRAG][2];
#pragma unroll
            for (int mi = 0; mi < 2; mi++) {
                int rb = wm + mi * 16;
                a[mi][0] = __float_as_uint(As[buf][(rb + g) * SA + ks + tig]);
                a[mi][1] = __float_as_uint(As[buf][(rb + g + 8) * SA + ks + tig]);
                a[mi][2] = __float_as_uint(As[buf][(rb + g) * SA + ks + tig + 4]);
                a[mi][3] = __float_as_uint(As[buf][(rb + g + 8) * SA + ks + tig + 4]);
            }
#pragma unroll
            for (int ni = 0; ni < NFRAG; ni++) {
                int cb = wn + ni * 8 + g;
                if (TB) {
                    bf[ni][0] = __float_as_uint(Bs[buf][cb * SBT + ks + tig]);
                    bf[ni][1] = __float_as_uint(Bs[buf][cb * SBT + ks + tig + 4]);
                } else {
                    bf[ni][0] = __float_as_uint(Bs[buf][(ks + tig) * SBN + cb]);
                    bf[ni][1] = __float_as_uint(Bs[buf][(ks + tig + 4) * SBN + cb]);
                }
            }
#pragma unroll
            for (int mi = 0; mi < 2; mi++)
#pragma unroll
                for (int ni = 0; ni < NFRAG; ni++)
                    mma_tf32(c[mi][ni], a[mi], bf[ni]);
        }
        if (has_next) {
            int nb = buf ^ 1;
            float* s = As[nb] + ar * SA + ak;
            s[0] = f2tf(pA0.x); s[1] = f2tf(pA0.y); s[2] = f2tf(pA0.z); s[3] = f2tf(pA0.w);
            s += 64 * SA;
            s[0] = f2tf(pA1.x); s[1] = f2tf(pA1.y); s[2] = f2tf(pA1.z); s[3] = f2tf(pA1.w);
            if (TB) {
                float* sb = Bs[nb] + ar * SBT + ak;
                sb[0] = f2tf(pB0.x); sb[1] = f2tf(pB0.y); sb[2] = f2tf(pB0.z); sb[3] = f2tf(pB0.w);
                sb += 64 * SBT;
                sb[0] = f2tf(pB1.x); sb[1] = f2tf(pB1.y); sb[2] = f2tf(pB1.z); sb[3] = f2tf(pB1.w);
            } else {
                float* sb = Bs[nb] + (t >> 4) * SBN + ((t & 15) << 2);
                float4 w0 = make_float4(f2tf(pB0.x), f2tf(pB0.y), f2tf(pB0.z), f2tf(pB0.w));
                *(float4*)(sb) = w0;
                if (BN == 128) {
                    float4 w1 = make_float4(f2tf(pB1.x), f2tf(pB1.y), f2tf(pB1.z), f2tf(pB1.w));
                    *(float4*)(sb + 64) = w1;
                }
            }
            __syncthreads();
            buf = nb;
        }
    }

#pragma unroll
    for (int mi = 0; mi < 2; mi++) {
#pragma unroll
        for (int ni = 0; ni < NFRAG; ni++) {
            int row = bm + wm + mi * 16 + g;
            int col = bn + wn + ni * 8 + tig * 2;
            *(float2*)(C + (size_t)row * N + col) = make_float2(c[mi][ni][0], c[mi][ni][1]);
            *(float2*)(C + (size_t)(row + 8) * N + col) = make_float2(c[mi][ni][2], c[mi][ni][3]);
            if (SYM && bm != bn) {
                // mirror: C[col][row] = C[row][col] (bit-identical)
                C[(size_t)col * N + row]           = c[mi][ni][0];
                C[(size_t)(col + 1) * N + row]     = c[mi][ni][1];
                C[(size_t)col * N + row + 8]       = c[mi][ni][2];
                C[(size_t)(col + 1) * N + row + 8] = c[mi][ni][3];
            }
        }
    }
}

// ---------------- row L2-normalize (in place) ----------------
__global__ void normalize_kernel(float* __restrict__ X, int D) {
    int r = blockIdx.x;
    int t = threadIdx.x;  // 128
    float s = 0.f;
    for (int j = t; j < D; j += 128) {
        float v = X[(size_t)r * D + j];
        s += v * v;
    }
    __shared__ float red[128];
    red[t] = s;
    __syncthreads();
    for (int w = 64; w > 0; w >>= 1) {
        if (t < w) red[t] += red[t + w];
        __syncthreads();
    }
    float norm = fmaxf(sqrtf(red[0]), 1e-8f);
    float inv = 1.0f / norm;
    for (int j = t; j < D; j += 128) X[(size_t)r * D + j] *= inv;
}

// ---------------- fused masked softmax + sparse matmul (exact, compacted) ----------------
__global__ __launch_bounds__(256)
void softmax_spmm_kernel(const float* __restrict__ Dm, const float* __restrict__ V,
                         const int* __restrict__ map, float* __restrict__ out, int vd) {
    __shared__ float sred[256];
    __shared__ int   sscan[256];
    __shared__ int   sel_idx[N_CLS];
    __shared__ float sel_w[N_CLS];

    int i = blockIdx.x;
    int t = threadIdx.x;
    const float* row = Dm + (size_t)i * N_CLS;

    float v[8];
#pragma unroll
    for (int q = 0; q < 8; q++) v[q] = row[t + q * 256];

    float lmax = -1e30f;
    int lcnt = 0;
#pragma unroll
    for (int q = 0; q < 8; q++) {
        if (v[q] > THRESH) { lmax = fmaxf(lmax, v[q]); lcnt++; }
    }

    sred[t] = lmax;
    sscan[t] = lcnt;
    __syncthreads();
    for (int w = 128; w > 0; w >>= 1) {
        if (t < w) sred[t] = fmaxf(sred[t], sred[t + w]);
        __syncthreads();
    }
    float m = sred[0];
    __syncthreads();
    for (int off = 1; off < 256; off <<= 1) {
        int val = (t >= off) ? sscan[t - off] : 0;
        __syncthreads();
        sscan[t] += val;
        __syncthreads();
    }
    int cnt = sscan[255];
    int base = sscan[t] - lcnt;

    float acc[8];
#pragma unroll
    for (int q = 0; q < 8; q++) acc[q] = 0.f;
    int nq = vd >> 8;

    if (cnt > 0) {
        float lsum = 0.f;
#pragma unroll
        for (int q = 0; q < 8; q++) {
            if (v[q] > THRESH) lsum += expf((v[q] - m) * TSOFT);
        }
        __syncthreads();
        sred[t] = lsum;
        __syncthreads();
        for (int w = 128; w > 0; w >>= 1) {
            if (t < w) sred[t] += sred[t + w];
            __syncthreads();
        }
        float invS = 1.0f / sred[0];

        int pos = base;
#pragma unroll
        for (int q = 0; q < 8; q++) {
            if (v[q] > THRESH) {
                sel_idx[pos] = t + q * 256;
                sel_w[pos] = expf((v[q] - m) * TSOFT) * invS;
                pos++;
            }
        }
        __syncthreads();

        for (int s = 0; s < cnt; s++) {
            int j = sel_idx[s];
            float w = sel_w[s];
            int src = map ? map[j] : j;
            const float* vr = V + (size_t)src * vd;
#pragma unroll
            for (int q = 0; q < 8; q++)
                if (q < nq) acc[q] += w * vr[t + q * 256];
        }
    } else {
        float w = 1.0f / (float)N_CLS;
        for (int j = 0; j < N_CLS; j++) {
            int src = map ? map[j] : j;
            const float* vr = V + (size_t)src * vd;
#pragma unroll
            for (int q = 0; q < 8; q++)
                if (q < nq) acc[q] += w * vr[t + q * 256];
        }
    }

#pragma unroll
    for (int q = 0; q < 8; q++)
        if (q < nq) out[(size_t)i * vd + t + q * 256] = acc[q];
}

// ---------------- launch ----------------
extern "C" void kernel_launch(void* const* d_in, const int* in_sizes, int n_in,
                              void* d_out, int out_size) {
    const float* image      = (const float*)d_in[0];
    const float* attributes = (const float*)d_in[1];
    const int*   labels     = (const int*)d_in[2];
    const int*   tpl        = (const int*)d_in[3];
    const float* ga         = (const float*)d_in[4];
    const float* gv         = (const float*)d_in[5];
    float* out = (float*)d_out;

    float *a1p, *dp, *aop, *prp;
    cudaGetSymbolAddress((void**)&a1p, g_a1);
    cudaGetSymbolAddress((void**)&dp, g_d);
    cudaGetSymbolAddress((void**)&aop, g_attouts);
    cudaGetSymbolAddress((void**)&prp, g_protos);

    const int NTRI = (N_CLS / 128) * (N_CLS / 128 + 1) / 2;  // 136

    // prototypes (segment mean)
    zero_counts_kernel<<<(N_CLS + 255) / 256, 256>>>();
    count_kernel<<<N_IMG / 256, 256>>>(labels);
    scan_kernel<<<1, 1024>>>();
    scatter_kernel<<<N_IMG / 256, 256>>>(labels);
    proto_kernel<<<dim3(N_CLS, 2), 256>>>(image);

    // a1 = attributes @ att_g_a ; normalize ; d1 = a1n @ a1n^T (symmetric)
    gemm_tc<false, 64, false><<<dim3(HC / 64, N_CLS / 128), 256>>>(attributes, ga, a1p, N_CLS, HC, ATT_D);
    normalize_kernel<<<N_CLS, 128>>>(a1p, HC);
    gemm_tc<true, 128, true><<<NTRI, 256>>>(a1p, a1p, dp, N_CLS, N_CLS, HC);

    // att_outs = softmax(mask(d1)) @ attributes   (exact sparse)
    softmax_spmm_kernel<<<N_CLS, 256>>>(dp, attributes, nullptr, aop, ATT_D);

    // a2 = att_outs @ att_g_v ; normalize ; d2 (symmetric)
    gemm_tc<false, 64, false><<<dim3(HC / 64, N_CLS / 128), 256>>>(aop, gv, a1p, N_CLS, HC, ATT_D);
    normalize_kernel<<<N_CLS, 128>>>(a1p, HC);
    gemm_tc<true, 128, true><<<NTRI, 256>>>(a1p, a1p, dp, N_CLS, N_CLS, HC);

    // out = softmax(mask(d2)) @ protos[tpl]   (exact sparse)
    softmax_spmm_kernel<<<N_CLS, 256>>>(dp, prp, tpl, out, IMG_D);
}

// round 5
// speedup vs baseline: 5.5888x; 1.1782x over previous
#include <cuda_runtime.h>
#include <math.h>

#define N_IMG   65536
#define IMG_D   2048
#define N_CLS   2048
#define ATT_D   1024
#define HC      512
#define TSOFT   10.0f
#define THRESH  0.17364817766693041f

// ---------------- scratch (static device memory; no allocation) ----------------
__device__ float g_a1[N_CLS * HC];
__device__ float g_d[N_CLS * N_CLS];
__device__ float g_attouts[N_CLS * ATT_D];
__device__ float g_protos[N_CLS * IMG_D];
__device__ int   g_count[N_CLS];
__device__ int   g_offset[N_CLS];
__device__ int   g_cursor[N_CLS];
__device__ int   g_perm[N_IMG];

// ---------------- segment mean: histogram / scan / scatter / gather ----------------
__global__ void zero_counts_kernel() {
    int i = blockIdx.x * blockDim.x + threadIdx.x;
    if (i < N_CLS) g_count[i] = 0;
}

__global__ void count_kernel(const int* __restrict__ labels) {
    int i = blockIdx.x * blockDim.x + threadIdx.x;
    if (i < N_IMG) atomicAdd(&g_count[labels[i]], 1);
}

__global__ void scan_kernel() {
    __shared__ int a[N_CLS];
    __shared__ int b[1024];
    int t = threadIdx.x;
    a[2 * t]     = g_count[2 * t];
    a[2 * t + 1] = g_count[2 * t + 1];
    __syncthreads();
    b[t] = a[2 * t] + a[2 * t + 1];
    __syncthreads();
    for (int off = 1; off < 1024; off <<= 1) {
        int v = (t >= off) ? b[t - off] : 0;
        __syncthreads();
        b[t] += v;
        __syncthreads();
    }
    int excl = (t == 0) ? 0 : b[t - 1];
    g_offset[2 * t]     = excl;
    g_offset[2 * t + 1] = excl + a[2 * t];
    g_cursor[2 * t]     = excl;
    g_cursor[2 * t + 1] = excl + a[2 * t];
}

__global__ void scatter_kernel(const int* __restrict__ labels) {
    int i = blockIdx.x * blockDim.x + threadIdx.x;
    if (i < N_IMG) {
        int l = labels[i];
        int pos = atomicAdd(&g_cursor[l], 1);
        g_perm[pos] = i;
    }
}

// grid (N_CLS, 2), 256 threads: each block averages 1024 cols of one class
__global__ void proto_kernel(const float* __restrict__ imgs) {
    int c = blockIdx.x;
    int col = blockIdx.y * 1024 + threadIdx.x * 4;
    int cnt  = g_count[c];
    int base = g_offset[c];
    float4 acc = make_float4(0.f, 0.f, 0.f, 0.f);
    int r = 0;
    for (; r + 4 <= cnt; r += 4) {
        int i0 = g_perm[base + r];
        int i1 = g_perm[base + r + 1];
        int i2 = g_perm[base + r + 2];
        int i3 = g_perm[base + r + 3];
        float4 v0 = *(const float4*)(imgs + (size_t)i0 * IMG_D + col);
        float4 v1 = *(const float4*)(imgs + (size_t)i1 * IMG_D + col);
        float4 v2 = *(const float4*)(imgs + (size_t)i2 * IMG_D + col);
        float4 v3 = *(const float4*)(imgs + (size_t)i3 * IMG_D + col);
        acc.x += (v0.x + v1.x) + (v2.x + v3.x);
        acc.y += (v0.y + v1.y) + (v2.y + v3.y);
        acc.z += (v0.z + v1.z) + (v2.z + v3.z);
        acc.w += (v0.w + v1.w) + (v2.w + v3.w);
    }
    for (; r < cnt; r++) {
        int i0 = g_perm[base + r];
        float4 v0 = *(const float4*)(imgs + (size_t)i0 * IMG_D + col);
        acc.x += v0.x; acc.y += v0.y; acc.z += v0.z; acc.w += v0.w;
    }
    float inv = (cnt > 0) ? (1.0f / (float)cnt) : 0.0f;
    acc.x *= inv; acc.y *= inv; acc.z *= inv; acc.w *= inv;
    *(float4*)(g_protos + (size_t)c * IMG_D + col) = acc;
}

// ---------------- TF32 tensor-core GEMM ----------------
__device__ __forceinline__ float f2tf(float x) {
    unsigned r;
    asm("cvt.rna.tf32.f32 %0, %1;" : "=r"(r) : "f"(x));
    return __uint_as_float(r);
}

__device__ __forceinline__ void mma_tf32(float* c, const unsigned* a, const unsigned* b) {
    asm volatile(
        "mma.sync.aligned.m16n8k8.row.col.f32.tf32.tf32.f32 "
        "{%0,%1,%2,%3}, {%4,%5,%6,%7}, {%8,%9}, {%0,%1,%2,%3};"
        : "+f"(c[0]), "+f"(c[1]), "+f"(c[2]), "+f"(c[3])
        : "r"(a[0]), "r"(a[1]), "r"(a[2]), "r"(a[3]), "r"(b[0]), "r"(b[1]));
}

// C[M,N] = A[M,K] @ (TB ? B[N,K]^T : B[K,N]).  128xBN x16 tiles, 8 warps.
// SYM: A==B (NT self-similarity); triangular grid, mirror-write transpose.
template <bool TB, int BN, bool SYM>
__global__ __launch_bounds__(256)
void gemm_tc(const float* __restrict__ A, const float* __restrict__ B,
             float* __restrict__ C, int M, int N, int K) {
    const int BM = 128, BK = 16;
    const int NFRAG = BN / 16;
    const int SA = 20;
    const int SBT = 20;
    const int SBN = BN + 4;
    const int BSZ = TB ? BN * SBT : BK * SBN;
    __shared__ float As[2][BM * SA];
    __shared__ float Bs[2][BSZ];

    int t = threadIdx.x;
    int warp = t >> 5, lane = t & 31, g = lane >> 2, tig = lane & 3;

    int bm, bn;
    if (SYM) {
        int bi = blockIdx.x, r = 0, rowlen = N / 128;
        while (bi >= rowlen) { bi -= rowlen; r++; rowlen--; }
        bm = r * 128;
        bn = (r + bi) * 128;
    } else {
        bm = blockIdx.y * BM;
        bn = blockIdx.x * BN;
    }
    int wm = (warp >> 1) * 32, wn = (warp & 1) * (BN / 2);

    int ar = t >> 2;
    int ak = (t & 3) << 2;

    const float* Ag = A + (size_t)(bm + ar) * K + ak;
    const float* Bg = TB ? (B + (size_t)(bn + ar) * K + ak)
                         : (B + (size_t)(t >> 4) * N + bn + ((t & 15) << 2));

    float c[2][NFRAG][4];
#pragma unroll
    for (int mi = 0; mi < 2; mi++)
#pragma unroll
        for (int ni = 0; ni < NFRAG; ni++)
#pragma unroll
            for (int q = 0; q < 4; q++) c[mi][ni][q] = 0.f;

    float4 pA0 = *(const float4*)(Ag);
    float4 pA1 = *(const float4*)(Ag + (size_t)64 * K);
    float4 pB0, pB1;
    if (TB) { pB0 = *(const float4*)(Bg); pB1 = *(const float4*)(Bg + (size_t)64 * K); }
    else    { pB0 = *(const float4*)(Bg); if (BN == 128) pB1 = *(const float4*)(Bg + 64); }

    int buf = 0;
    {
        float* s = As[0] + ar * SA + ak;
        s[0] = f2tf(pA0.x); s[1] = f2tf(pA0.y); s[2] = f2tf(pA0.z); s[3] = f2tf(pA0.w);
        s += 64 * SA;
        s[0] = f2tf(pA1.x); s[1] = f2tf(pA1.y); s[2] = f2tf(pA1.z); s[3] = f2tf(pA1.w);
        if (TB) {
            float* sb = Bs[0] + ar * SBT + ak;
            sb[0] = f2tf(pB0.x); sb[1] = f2tf(pB0.y); sb[2] = f2tf(pB0.z); sb[3] = f2tf(pB0.w);
            sb += 64 * SBT;
            sb[0] = f2tf(pB1.x); sb[1] = f2tf(pB1.y); sb[2] = f2tf(pB1.z); sb[3] = f2tf(pB1.w);
        } else {
            float* sb = Bs[0] + (t >> 4) * SBN + ((t & 15) << 2);
            float4 w0 = make_float4(f2tf(pB0.x), f2tf(pB0.y), f2tf(pB0.z), f2tf(pB0.w));
            *(float4*)(sb) = w0;
            if (BN == 128) {
                float4 w1 = make_float4(f2tf(pB1.x), f2tf(pB1.y), f2tf(pB1.z), f2tf(pB1.w));
                *(float4*)(sb + 64) = w1;
            }
        }
    }
    __syncthreads();

    int T = K / BK;
    for (int kt = 0; kt < T; kt++) {
        bool has_next = (kt + 1 < T);
        if (has_next) {
            Ag += BK;
            pA0 = *(const float4*)(Ag);
            pA1 = *(const float4*)(Ag + (size_t)64 * K);
            if (TB) {
                Bg += BK;
                pB0 = *(const float4*)(Bg);
                pB1 = *(const float4*)(Bg + (size_t)64 * K);
            } else {
                Bg += (size_t)BK * N;
                pB0 = *(const float4*)(Bg);
                if (BN == 128) pB1 = *(const float4*)(Bg + 64);
            }
        }
#pragma unroll
        for (int ks = 0; ks < BK; ks += 8) {
            unsigned a[2][4], bf[NFRAG][2];
#pragma unroll
            for (int mi = 0; mi < 2; mi++) {
                int rb = wm + mi * 16;
                a[mi][0] = __float_as_uint(As[buf][(rb + g) * SA + ks + tig]);
                a[mi][1] = __float_as_uint(As[buf][(rb + g + 8) * SA + ks + tig]);
                a[mi][2] = __float_as_uint(As[buf][(rb + g) * SA + ks + tig + 4]);
                a[mi][3] = __float_as_uint(As[buf][(rb + g + 8) * SA + ks + tig + 4]);
            }
#pragma unroll
            for (int ni = 0; ni < NFRAG; ni++) {
                int cb = wn + ni * 8 + g;
                if (TB) {
                    bf[ni][0] = __float_as_uint(Bs[buf][cb * SBT + ks + tig]);
                    bf[ni][1] = __float_as_uint(Bs[buf][cb * SBT + ks + tig + 4]);
                } else {
                    bf[ni][0] = __float_as_uint(Bs[buf][(ks + tig) * SBN + cb]);
                    bf[ni][1] = __float_as_uint(Bs[buf][(ks + tig + 4) * SBN + cb]);
                }
            }
#pragma unroll
            for (int mi = 0; mi < 2; mi++)
#pragma unroll
                for (int ni = 0; ni < NFRAG; ni++)
                    mma_tf32(c[mi][ni], a[mi], bf[ni]);
        }
        if (has_next) {
            int nb = buf ^ 1;
            float* s = As[nb] + ar * SA + ak;
            s[0] = f2tf(pA0.x); s[1] = f2tf(pA0.y); s[2] = f2tf(pA0.z); s[3] = f2tf(pA0.w);
            s += 64 * SA;
            s[0] = f2tf(pA1.x); s[1] = f2tf(pA1.y); s[2] = f2tf(pA1.z); s[3] = f2tf(pA1.w);
            if (TB) {
                float* sb = Bs[nb] + ar * SBT + ak;
                sb[0] = f2tf(pB0.x); sb[1] = f2tf(pB0.y); sb[2] = f2tf(pB0.z); sb[3] = f2tf(pB0.w);
                sb += 64 * SBT;
                sb[0] = f2tf(pB1.x); sb[1] = f2tf(pB1.y); sb[2] = f2tf(pB1.z); sb[3] = f2tf(pB1.w);
            } else {
                float* sb = Bs[nb] + (t >> 4) * SBN + ((t & 15) << 2);
                float4 w0 = make_float4(f2tf(pB0.x), f2tf(pB0.y), f2tf(pB0.z), f2tf(pB0.w));
                *(float4*)(sb) = w0;
                if (BN == 128) {
                    float4 w1 = make_float4(f2tf(pB1.x), f2tf(pB1.y), f2tf(pB1.z), f2tf(pB1.w));
                    *(float4*)(sb + 64) = w1;
                }
            }
            __syncthreads();
            buf = nb;
        }
    }

#pragma unroll
    for (int mi = 0; mi < 2; mi++) {
#pragma unroll
        for (int ni = 0; ni < NFRAG; ni++) {
            int row = bm + wm + mi * 16 + g;
            int col = bn + wn + ni * 8 + tig * 2;
            *(float2*)(C + (size_t)row * N + col) = make_float2(c[mi][ni][0], c[mi][ni][1]);
            *(float2*)(C + (size_t)(row + 8) * N + col) = make_float2(c[mi][ni][2], c[mi][ni][3]);
            if (SYM && bm != bn) {
                C[(size_t)col * N + row]           = c[mi][ni][0];
                C[(size_t)(col + 1) * N + row]     = c[mi][ni][1];
                C[(size_t)col * N + row + 8]       = c[mi][ni][2];
                C[(size_t)(col + 1) * N + row + 8] = c[mi][ni][3];
            }
        }
    }
}

// ---------------- row L2-normalize (in place) ----------------
__global__ void normalize_kernel(float* __restrict__ X, int D) {
    int r = blockIdx.x;
    int t = threadIdx.x;  // 128
    float s = 0.f;
    for (int j = t; j < D; j += 128) {
        float v = X[(size_t)r * D + j];
        s += v * v;
    }
    __shared__ float red[128];
    red[t] = s;
    __syncthreads();
    for (int w = 64; w > 0; w >>= 1) {
        if (t < w) red[t] += red[t + w];
        __syncthreads();
    }
    float norm = fmaxf(sqrtf(red[0]), 1e-8f);
    float inv = 1.0f / norm;
    for (int j = t; j < D; j += 128) X[(size_t)r * D + j] *= inv;
}

// ---------------- fused masked softmax + sparse matmul (exact, compacted) ----------------
__global__ __launch_bounds__(256)
void softmax_spmm_kernel(const float* __restrict__ Dm, const float* __restrict__ V,
                         const int* __restrict__ map, float* __restrict__ out, int vd) {
    __shared__ float sred[256];
    __shared__ int   sscan[256];
    __shared__ int   sel_idx[N_CLS];
    __shared__ float sel_w[N_CLS];

    int i = blockIdx.x;
    int t = threadIdx.x;
    const float* row = Dm + (size_t)i * N_CLS;

    float v[8];
#pragma unroll
    for (int q = 0; q < 8; q++) v[q] = row[t + q * 256];

    float lmax = -1e30f;
    int lcnt = 0;
#pragma unroll
    for (int q = 0; q < 8; q++) {
        if (v[q] > THRESH) { lmax = fmaxf(lmax, v[q]); lcnt++; }
    }

    sred[t] = lmax;
    sscan[t] = lcnt;
    __syncthreads();
    for (int w = 128; w > 0; w >>= 1) {
        if (t < w) sred[t] = fmaxf(sred[t], sred[t + w]);
        __syncthreads();
    }
    float m = sred[0];
    __syncthreads();
    for (int off = 1; off < 256; off <<= 1) {
        int val = (t >= off) ? sscan[t - off] : 0;
        __syncthreads();
        sscan[t] += val;
        __syncthreads();
    }
    int cnt = sscan[255];
    int base = sscan[t] - lcnt;

    float acc[8];
#pragma unroll
    for (int q = 0; q < 8; q++) acc[q] = 0.f;
    int nq = vd >> 8;

    if (cnt > 0) {
        float lsum = 0.f;
#pragma unroll
        for (int q = 0; q < 8; q++) {
            if (v[q] > THRESH) lsum += expf((v[q] - m) * TSOFT);
        }
        __syncthreads();
        sred[t] = lsum;
        __syncthreads();
        for (int w = 128; w > 0; w >>= 1) {
            if (t < w) sred[t] += sred[t + w];
            __syncthreads();
        }
        float invS = 1.0f / sred[0];

        int pos = base;
#pragma unroll
        for (int q = 0; q < 8; q++) {
            if (v[q] > THRESH) {
                sel_idx[pos] = t + q * 256;
                sel_w[pos] = expf((v[q] - m) * TSOFT) * invS;
                pos++;
            }
        }
        __syncthreads();

        for (int s = 0; s < cnt; s++) {
            int j = sel_idx[s];
            float w = sel_w[s];
            int src = map ? map[j] : j;
            const float* vr = V + (size_t)src * vd;
#pragma unroll
            for (int q = 0; q < 8; q++)
                if (q < nq) acc[q] += w * vr[t + q * 256];
        }
    } else {
        float w = 1.0f / (float)N_CLS;
        for (int j = 0; j < N_CLS; j++) {
            int src = map ? map[j] : j;
            const float* vr = V + (size_t)src * vd;
#pragma unroll
            for (int q = 0; q < 8; q++)
                if (q < nq) acc[q] += w * vr[t + q * 256];
        }
    }

#pragma unroll
    for (int q = 0; q < 8; q++)
        if (q < nq) out[(size_t)i * vd + t + q * 256] = acc[q];
}

// ---------------- launch ----------------
extern "C" void kernel_launch(void* const* d_in, const int* in_sizes, int n_in,
                              void* d_out, int out_size) {
    const float* image      = (const float*)d_in[0];
    const float* attributes = (const float*)d_in[1];
    const int*   labels     = (const int*)d_in[2];
    const int*   tpl        = (const int*)d_in[3];
    const float* ga         = (const float*)d_in[4];
    const float* gv         = (const float*)d_in[5];
    float* out = (float*)d_out;

    float *a1p, *dp, *aop, *prp;
    cudaGetSymbolAddress((void**)&a1p, g_a1);
    cudaGetSymbolAddress((void**)&dp, g_d);
    cudaGetSymbolAddress((void**)&aop, g_attouts);
    cudaGetSymbolAddress((void**)&prp, g_protos);

    // lazy one-time host-side handles (no device memory involved)
    static cudaStream_t s_proto = nullptr;
    static cudaEvent_t ev_fork = nullptr, ev_join = nullptr;
    if (!s_proto) {
        cudaStreamCreateWithFlags(&s_proto, cudaStreamNonBlocking);
        cudaEventCreateWithFlags(&ev_fork, cudaEventDisableTiming);
        cudaEventCreateWithFlags(&ev_join, cudaEventDisableTiming);
    }

    const int NTRI = (N_CLS / 128) * (N_CLS / 128 + 1) / 2;  // 136

    // ---- fork: proto chain on side stream (independent of attention chain) ----
    cudaEventRecord(ev_fork, 0);
    cudaStreamWaitEvent(s_proto, ev_fork, 0);

    zero_counts_kernel<<<(N_CLS + 255) / 256, 256, 0, s_proto>>>();
    count_kernel<<<N_IMG / 256, 256, 0, s_proto>>>(labels);
    scan_kernel<<<1, 1024, 0, s_proto>>>();
    scatter_kernel<<<N_IMG / 256, 256, 0, s_proto>>>(labels);
    proto_kernel<<<dim3(N_CLS, 2), 256, 0, s_proto>>>(image);
    cudaEventRecord(ev_join, s_proto);

    // ---- attention chain on main (capture) stream ----
    gemm_tc<false, 64, false><<<dim3(HC / 64, N_CLS / 128), 256>>>(attributes, ga, a1p, N_CLS, HC, ATT_D);
    normalize_kernel<<<N_CLS, 128>>>(a1p, HC);
    gemm_tc<true, 128, true><<<NTRI, 256>>>(a1p, a1p, dp, N_CLS, N_CLS, HC);
    softmax_spmm_kernel<<<N_CLS, 256>>>(dp, attributes, nullptr, aop, ATT_D);
    gemm_tc<false, 64, false><<<dim3(HC / 64, N_CLS / 128), 256>>>(aop, gv, a1p, N_CLS, HC, ATT_D);
    normalize_kernel<<<N_CLS, 128>>>(a1p, HC);
    gemm_tc<true, 128, true><<<NTRI, 256>>>(a1p, a1p, dp, N_CLS, N_CLS, HC);

    // ---- join, then final output spmm needs both chains ----
    cudaStreamWaitEvent(0, ev_join, 0);
    softmax_spmm_kernel<<<N_CLS, 256>>>(dp, prp, tpl, out, IMG_D);
}